// round 17
// baseline (speedup 1.0000x reference)
#include <cuda_runtime.h>
#include <cuda_fp16.h>
#include <cstdint>

#define HID 256
#define NB 32
#define NS 8192
#define NTILES 2048
#define GRID_MAIN 148

// SMEM byte offsets (main kernel)
#define SA_HI 0          // A plane: 128 rows x 512B (f16) = 64KB
#define SB    65536      // B resident: 8 chunks x 16KB = 128KB (persistent)
#define SCS   196608     // c[b,*] 1KB
#define SVS   197632     // v 1KB
#define SLOG  198656     // 128 rows x 2 slots floats = 1KB
#define SES   199680     // 128 exp values = 512B
#define SRED  200192     // reduce scratch
#define SCOMB 200704     // ctx combine scratch: 256 float4 = 4KB
#define SMEM_MAIN 204800

__device__ float    g_c[NB * HID];
__device__ uint32_t g_whi[HID * 128];     // We f16, [k_out][h/2] f16x2
__device__ float    g_pctx[NTILES * HID]; // per-tile unnormalized context
__device__ float    g_msum[NTILES * 2];   // per-tile (max, sum_exp)

// ---------------- helpers ----------------
__device__ __forceinline__ uint32_t cvta_smem(const void* p) {
    uint32_t a;
    asm("{ .reg .u64 t; cvta.to.shared.u64 t, %1; cvt.u32.u64 %0, t; }" : "=r"(a) : "l"(p));
    return a;
}
__device__ __forceinline__ uint32_t pack_f16(float x0, float x1) {
    uint32_t r;
    asm("cvt.rn.f16x2.f32 %0, %1, %2;" : "=r"(r) : "f"(x1), "f"(x0));
    return r;
}
__device__ __forceinline__ void sts128(uint32_t a, uint32_t x, uint32_t y, uint32_t z, uint32_t w) {
    asm volatile("st.shared.v4.b32 [%0], {%1,%2,%3,%4};" :: "r"(a), "r"(x), "r"(y), "r"(z), "r"(w) : "memory");
}
__device__ __forceinline__ void cp_async16(uint32_t saddr, const void* gptr) {
    uint64_t g;
    asm("cvta.to.global.u64 %0, %1;" : "=l"(g) : "l"(gptr));
    asm volatile("cp.async.cg.shared.global [%0], [%1], 16;" :: "r"(saddr), "l"(g) : "memory");
}
// fast, accurate tanh: err ~1e-6 (EX2 + fast divide)
__device__ __forceinline__ float fast_tanh(float x) {
    float e = __expf(-2.0f * fabsf(x));
    float t = __fdividef(1.0f - e, 1.0f + e);
    return copysignf(t, x);
}
// fp16 x fp16, fp32 accumulate
__device__ __forceinline__ void mma_f32(float* c,
        const uint32_t* a, uint32_t b0, uint32_t b1) {
    asm("mma.sync.aligned.m16n8k16.row.col.f32.f16.f16.f32 "
        "{%0,%1,%2,%3}, {%4,%5,%6,%7}, {%8,%9}, {%0,%1,%2,%3};"
        : "+f"(c[0]), "+f"(c[1]), "+f"(c[2]), "+f"(c[3])
        : "r"(a[0]), "r"(a[1]), "r"(a[2]), "r"(a[3]), "r"(b0), "r"(b1));
}
#define LDM4(r, a) \
    asm volatile("ldmatrix.sync.aligned.m8n8.x4.shared.b16 {%0,%1,%2,%3}, [%4];" \
        : "=r"((r)[0]), "=r"((r)[1]), "=r"((r)[2]), "=r"((r)[3]) : "r"(a))

// one N-pass of 16 ksteps (pass selects B half)
__device__ __forceinline__ void mma_pass(uint32_t S, int pass,
        uint32_t aBase0, uint32_t aBase1, uint32_t ghalfA, uint32_t sA,
        uint32_t ghalfB, uint32_t sBl, uint32_t bRow0, float accF[2][8][4])
{
#pragma unroll 1
    for (int cc = 0; cc < 4; cc++) {
        uint32_t Bbuf = S + SB + (uint32_t)(pass * 4 + cc) * 16384u;
#pragma unroll
        for (int ks = 0; ks < 4; ks++) {
            int kg = (cc << 2) + ks;
            uint32_t offA = (((uint32_t)(2 * kg) + ghalfA) ^ sA) << 4;
            uint32_t ah0[4], ah1[4];
            LDM4(ah0, aBase0 + offA);
            LDM4(ah1, aBase1 + offA);

            uint32_t offB = (((uint32_t)(2 * ks) + ghalfB) ^ sBl) << 4;
            uint32_t bh[4][4];
            uint32_t bAh = Bbuf + bRow0 + offB;
#pragma unroll
            for (int g = 0; g < 4; g++)
                LDM4(bh[g], bAh + (uint32_t)g * 2048u);
#pragma unroll
            for (int g = 0; g < 4; g++) {
#pragma unroll
                for (int sub = 0; sub < 2; sub++) {
                    int ni = 2 * g + sub;
                    mma_f32(accF[0][ni], ah0, bh[g][2 * sub], bh[g][2 * sub + 1]);
                    mma_f32(accF[1][ni], ah1, bh[g][2 * sub], bh[g][2 * sub + 1]);
                }
            }
        }
    }
}

// ---------------------------------------------------------------------------
// merged prep: blocks [0,128) convert We -> f16 plane; blocks [128,256)
// compute c: block id = 128 + b*4 + q covers batch b, k in [q*64, q*64+64).
// 4 threads per k (each 64 h), shfl-reduce.
// ---------------------------------------------------------------------------
__global__ void prep_kernel(const float* __restrict__ W,
                            const float* __restrict__ hidden,
                            const float* __restrict__ bias) {
    __shared__ float hs[HID];
    int t = threadIdx.x;
    if (blockIdx.x < 128) {
        int idx = blockIdx.x * 256 + t;  // 0..32767
        int n = idx >> 7, wp = idx & 127;
        float x0 = W[n * 512 + 256 + wp * 2];
        float x1 = W[n * 512 + 257 + wp * 2];
        g_whi[idx] = pack_f16(x0, x1);
    } else {
        int id = blockIdx.x - 128;    // 0..127
        int b = id >> 2, q = id & 3;
        hs[t] = hidden[b * HID + t];
        __syncthreads();
        int kl = t >> 2, hq = t & 3;
        int k = q * 64 + kl;
        const float4* wr = ((const float4*)(W + (size_t)k * (2 * HID))) + hq * 16;
        const float* hp = hs + hq * 64;
        float a0 = 0.f, a1 = 0.f;
#pragma unroll
        for (int i = 0; i < 16; i += 2) {
            float4 w0 = wr[i], w1 = wr[i + 1];
            a0 += w0.x * hp[4 * i + 0] + w0.y * hp[4 * i + 1]
                + w0.z * hp[4 * i + 2] + w0.w * hp[4 * i + 3];
            a1 += w1.x * hp[4 * i + 4] + w1.y * hp[4 * i + 5]
                + w1.z * hp[4 * i + 6] + w1.w * hp[4 * i + 7];
        }
        float acc = a0 + a1;
        acc += __shfl_down_sync(0xffffffffu, acc, 2);
        acc += __shfl_down_sync(0xffffffffu, acc, 1);
        if (hq == 0) g_c[b * HID + k] = acc + bias[k];
    }
}

// ---------------------------------------------------------------------------
// Main fused kernel: persistent CTAs, resident B. Pass-0 epilogue is
// interleaved into the pass-1 MMA loop (dual accumulator sets); pass-1
// epilogue interleaved with next-tile A prefetch.
// ---------------------------------------------------------------------------
__global__ void __launch_bounds__(256, 1) main_mma_kernel(
    const float* __restrict__ enc, const float* __restrict__ v,
    float* __restrict__ attn)
{
    extern __shared__ char smem[];
    const uint32_t S = cvta_smem(smem);

    int t = threadIdx.x;
    int lane = t & 31, w = t >> 5;
    int grp = lane >> 2, tig = lane & 3;
    int mbase = (w & 3) * 32;
    int nb    = (w >> 2) * 64;

    // ldmatrix lane addressing
    int lrow   = lane & 15;
    uint32_t ghalfA = (uint32_t)(lane >> 4);
    uint32_t sA     = (uint32_t)(lrow & 7);
    uint32_t aBase0 = S + SA_HI + (uint32_t)(mbase + lrow) * 512u;
    uint32_t aBase1 = aBase0 + 16u * 512u;
    uint32_t ghalfB = (uint32_t)((lane >> 3) & 1);
    uint32_t sBl    = (uint32_t)(lane & 7);
    uint32_t bRow0  = ((uint32_t)(nb + (lane & 7) + ((lane >> 4) & 1) * 8)) * 128u;

    // per-thread A staging: 2 threads per row, 128 floats each
    const int arow  = t >> 1;
    const int ahalf = t & 1;
    const uint32_t awbase = (uint32_t)arow * 128 + (uint32_t)ahalf * 64;
    const uint32_t asz    = ((uint32_t)arow & 7) << 2;

    ((float*)(smem + SVS))[t] = v[t];

    // ---- prefetch ALL of B (8 chunks x 16KB), ONCE per CTA ----
    {
        int n  = t >> 1;
        int wq = (t & 1) * 16;
        uint32_t sz   = ((uint32_t)n & 7) << 2;
        uint32_t wrow = (uint32_t)n * 32;
#pragma unroll
        for (int q = 0; q < 8; q++) {
            int p = q >> 2, cc = q & 3;
            uint32_t buf = S + SB + (uint32_t)q * 16384u;
            const uint32_t* src = g_whi + (size_t)(p * 128 + n) * 128 + cc * 32 + wq;
#pragma unroll
            for (int j = 0; j < 4; j++) {
                uint32_t wc = (uint32_t)(wq + j * 4);
                cp_async16(buf + ((wrow + (wc ^ sz)) << 2), src + j * 4);
            }
        }
        asm volatile("cp.async.commit_group;" ::: "memory");
        asm volatile("cp.async.wait_group 0;" ::: "memory");
    }

    // ---- load + convert + STS A for FIRST tile ----
    {
        int tile0 = blockIdx.x;
        size_t rb0 = (size_t)(tile0 >> 6) * NS + (size_t)(tile0 & 63) * 128;
        const float4* src = ((const float4*)(enc + (rb0 + (size_t)arow) * HID)) + ahalf * 32;
#pragma unroll 4
        for (int j = 0; j < 16; j++) {
            float4 f0 = src[2 * j], f1 = src[2 * j + 1];
            uint32_t h0 = pack_f16(f0.x, f0.y);
            uint32_t h1 = pack_f16(f0.z, f0.w);
            uint32_t h2 = pack_f16(f1.x, f1.y);
            uint32_t h3 = pack_f16(f1.z, f1.w);
            uint32_t wd = awbase + (uint32_t)j * 4;
            sts128(S + SA_HI + ((wd ^ asz) << 2), h0, h1, h2, h3);
        }
    }

    float accF0[2][8][4] = {};
    const float* cs_all = (const float*)(smem + SCS);
    const float* vs_all = (const float*)(smem + SVS);
    float* slog = (float*)(smem + SLOG);
    float* redm = (float*)(smem + SRED);
    float* reds = (float*)(smem + SRED + 16);
    float* es   = (float*)(smem + SES);

    for (int tile = blockIdx.x; tile < NTILES; tile += GRID_MAIN) {
        int b  = tile >> 6;
        size_t rowbase = (size_t)b * NS + (size_t)(tile & 63) * 128;
        int next = tile + GRID_MAIN;
        bool has_next = (next < NTILES);

        // stage c[b,*], zero slog; barrier publishes these AND the A plane
        ((float*)(smem + SCS))[t] = g_c[b * HID + t];
        slog[t] = 0.f;
        __syncthreads();

        // ---- pass 0: MMA only (epilogue deferred into pass-1 loop) ----
        mma_pass(S, 0, aBase0, aBase1, ghalfA, sA, ghalfB, sBl, bRow0, accF0);

        // ---- pass 1 MMA with pass-0 epilogue slices interleaved ----
        float accF1[2][8][4] = {};
        float s0m0[2] = {0.f, 0.f}, s1m0[2] = {0.f, 0.f};
#pragma unroll 1
        for (int cc = 0; cc < 4; cc++) {
            uint32_t Bbuf = S + SB + (uint32_t)(4 + cc) * 16384u;
#pragma unroll
            for (int ks = 0; ks < 4; ks++) {
                int kg = (cc << 2) + ks;
                uint32_t offA = (((uint32_t)(2 * kg) + ghalfA) ^ sA) << 4;
                uint32_t ah0[4], ah1[4];
                LDM4(ah0, aBase0 + offA);
                LDM4(ah1, aBase1 + offA);

                uint32_t offB = (((uint32_t)(2 * ks) + ghalfB) ^ sBl) << 4;
                uint32_t bh[4][4];
                uint32_t bAh = Bbuf + bRow0 + offB;
#pragma unroll
                for (int g = 0; g < 4; g++)
                    LDM4(bh[g], bAh + (uint32_t)g * 2048u);
#pragma unroll
                for (int g = 0; g < 4; g++) {
#pragma unroll
                    for (int sub = 0; sub < 2; sub++) {
                        int ni = 2 * g + sub;
                        mma_f32(accF1[0][ni], ah0, bh[g][2 * sub], bh[g][2 * sub + 1]);
                        mma_f32(accF1[1][ni], ah1, bh[g][2 * sub], bh[g][2 * sub + 1]);
                    }
                }
                // -- pass-0 epilogue slice (hides under tensor-pipe work) --
                {
                    int mi = kg & 1, ni = kg >> 1;
                    int c0 = nb + ni * 8 + tig * 2;
                    float vv0 = vs_all[c0], vv1 = vs_all[c0 + 1];
                    float cc0 = cs_all[c0], cc1 = cs_all[c0 + 1];
                    s0m0[mi] += vv0 * fast_tanh(accF0[mi][ni][0] + cc0)
                              + vv1 * fast_tanh(accF0[mi][ni][1] + cc1);
                    s1m0[mi] += vv0 * fast_tanh(accF0[mi][ni][2] + cc0)
                              + vv1 * fast_tanh(accF0[mi][ni][3] + cc1);
#pragma unroll
                    for (int j = 0; j < 4; j++) accF0[mi][ni][j] = 0.f;
                }
            }
        }
        // reduce + store pass-0 logit partials
#pragma unroll
        for (int mi = 0; mi < 2; mi++) {
            float s0 = s0m0[mi], s1 = s1m0[mi];
            s0 += __shfl_xor_sync(0xffffffffu, s0, 1);
            s0 += __shfl_xor_sync(0xffffffffu, s0, 2);
            s1 += __shfl_xor_sync(0xffffffffu, s1, 1);
            s1 += __shfl_xor_sync(0xffffffffu, s1, 2);
            if (tig == 0) {
                int r0 = mbase + mi * 16 + grp;
                slog[r0 * 2 + (w >> 2)]       += s0;
                slog[(r0 + 8) * 2 + (w >> 2)] += s1;
            }
        }
        __syncthreads();   // all A-plane ldmatrix reads complete

        // ---- pass-1 epilogue INTERLEAVED with next-tile A prefetch ----
        {
            const float4* srcn = nullptr;
            if (has_next) {
                size_t rbn = (size_t)(next >> 6) * NS + (size_t)(next & 63) * 128;
                srcn = ((const float4*)(enc + (rbn + (size_t)arow) * HID)) + ahalf * 32;
            }
            const float* cs = cs_all + 128;
            const float* vs = vs_all + 128;
            float s0m[2] = {0.f, 0.f}, s1m[2] = {0.f, 0.f};
#pragma unroll
            for (int ch = 0; ch < 4; ch++) {
                float4 fr[8];
                if (has_next) {
#pragma unroll
                    for (int j = 0; j < 8; j++) fr[j] = srcn[ch * 8 + j];
                }
#pragma unroll
                for (int mi = 0; mi < 2; mi++) {
#pragma unroll
                    for (int nn = 0; nn < 2; nn++) {
                        int ni = 2 * ch + nn;
                        int c0 = nb + ni * 8 + tig * 2;
                        float vv0 = vs[c0], vv1 = vs[c0 + 1];
                        float cc0 = cs[c0], cc1 = cs[c0 + 1];
                        s0m[mi] += vv0 * fast_tanh(accF1[mi][ni][0] + cc0)
                                 + vv1 * fast_tanh(accF1[mi][ni][1] + cc1);
                        s1m[mi] += vv0 * fast_tanh(accF1[mi][ni][2] + cc0)
                                 + vv1 * fast_tanh(accF1[mi][ni][3] + cc1);
                    }
                }
                if (has_next) {
#pragma unroll
                    for (int jj = 0; jj < 4; jj++) {
                        float4 f0 = fr[2 * jj], f1 = fr[2 * jj + 1];
                        uint32_t h0 = pack_f16(f0.x, f0.y);
                        uint32_t h1 = pack_f16(f0.z, f0.w);
                        uint32_t h2 = pack_f16(f1.x, f1.y);
                        uint32_t h3 = pack_f16(f1.z, f1.w);
                        uint32_t wd = awbase + (uint32_t)(ch * 4 + jj) * 4;
                        sts128(S + SA_HI + ((wd ^ asz) << 2), h0, h1, h2, h3);
                    }
                }
            }
#pragma unroll
            for (int mi = 0; mi < 2; mi++) {
                float s0 = s0m[mi], s1 = s1m[mi];
                s0 += __shfl_xor_sync(0xffffffffu, s0, 1);
                s0 += __shfl_xor_sync(0xffffffffu, s0, 2);
                s1 += __shfl_xor_sync(0xffffffffu, s1, 1);
                s1 += __shfl_xor_sync(0xffffffffu, s1, 2);
                if (tig == 0) {
                    int r0 = mbase + mi * 16 + grp;
                    slog[r0 * 2 + (w >> 2)]       += s0;
                    slog[(r0 + 8) * 2 + (w >> 2)] += s1;
                }
            }
        }
        __syncthreads();

        // ---- finalize logits, per-tile softmax stats ----
        float logit = 0.f;
        if (t < 128) {
            logit = slog[t * 2] + slog[t * 2 + 1];
            attn[rowbase + t] = logit;
            float m = logit;
#pragma unroll
            for (int off = 16; off > 0; off >>= 1)
                m = fmaxf(m, __shfl_xor_sync(0xffffffffu, m, off));
            if (lane == 0) redm[t >> 5] = m;
        }
        __syncthreads();
        float m_tile = fmaxf(fmaxf(redm[0], redm[1]), fmaxf(redm[2], redm[3]));
        if (t < 128) {
            float e = __expf(logit - m_tile);
            es[t] = e;
            float se = e;
#pragma unroll
            for (int off = 16; off > 0; off >>= 1)
                se += __shfl_xor_sync(0xffffffffu, se, off);
            if (lane == 0) reds[t >> 5] = se;
        }
        __syncthreads();   // publishes es[] to all threads
        if (t == 0) {
            g_msum[tile * 2]     = m_tile;
            g_msum[tile * 2 + 1] = (reds[0] + reds[1]) + (reds[2] + reds[3]);
        }

        // ---- partial context from GLOBAL fp32 enc (L2-hot) ----
        {
            int h4 = t & 63, sg = t >> 6;
            const float4* e4 = (const float4*)(enc + rowbase * HID);
            float4 a4 = make_float4(0.f, 0.f, 0.f, 0.f);
#pragma unroll 4
            for (int s = sg; s < 128; s += 4) {
                float e = es[s];
                float4 x = e4[(size_t)s * 64 + h4];
                a4.x += e * x.x; a4.y += e * x.y;
                a4.z += e * x.z; a4.w += e * x.w;
            }
            float4* comb = (float4*)(smem + SCOMB);
            comb[t] = a4;
            __syncthreads();
            if (t < 64) {
                float4 a = comb[t], bq = comb[t + 64], c = comb[t + 128], d = comb[t + 192];
                float4 r;
                r.x = (a.x + bq.x) + (c.x + d.x);
                r.y = (a.y + bq.y) + (c.y + d.y);
                r.z = (a.z + bq.z) + (c.z + d.z);
                r.w = (a.w + bq.w) + (c.w + d.w);
                ((float4*)(g_pctx + (size_t)tile * HID))[t] = r;
            }
        }
        // next loop-top barrier publishes the already-written next A plane
    }
}

// ---------------------------------------------------------------------------
// finalize: grid (NB, 8) x 256. Parallel (M, D) reduce over 64 tile-stats,
// normalize 1/8 of attn per block; y==0 blocks combine partial contexts.
// ---------------------------------------------------------------------------
__global__ void finalize_kernel(float* __restrict__ attn, float* __restrict__ ctx) {
    __shared__ float sm[64], ss[64], sc[64];
    __shared__ float red[64];
    __shared__ float sMD[2];
    int b = blockIdx.x;
    int seg = blockIdx.y;
    int t = threadIdx.x;   // 256

    if (t < 64) {
        sm[t] = g_msum[(b * 64 + t) * 2];
        ss[t] = g_msum[(b * 64 + t) * 2 + 1];
        red[t] = sm[t];
    }
    __syncthreads();
    if (t < 32) red[t] = fmaxf(red[t], red[t + 32]);
    __syncthreads();
    if (t == 0) {
        float M = red[0];
#pragma unroll
        for (int i = 1; i < 32; i++) M = fmaxf(M, red[i]);
        sMD[0] = M;
    }
    __syncthreads();
    float M = sMD[0];
    if (t < 64) {
        float sci = __expf(sm[t] - M);
        sc[t] = sci;
        red[t] = sci * ss[t];
    }
    __syncthreads();
    if (t == 0) {
        float D = 0.f;
#pragma unroll
        for (int i = 0; i < 64; i++) D += red[i];
        sMD[1] = __fdividef(1.f, D);
    }
    __syncthreads();
    float invD = sMD[1];

    // normalize this block's 1024-logit slice
    float4* row = (float4*)(attn + (size_t)b * NS + (size_t)seg * (NS / 8));
    {
        float4 x = row[t];
        x.x = __expf(x.x - M) * invD;
        x.y = __expf(x.y - M) * invD;
        x.z = __expf(x.z - M) * invD;
        x.w = __expf(x.w - M) * invD;
        row[t] = x;
    }

    // ctx combine (one block per batch)
    if (seg == 0) {
        float acc = 0.f;
#pragma unroll 8
        for (int i = 0; i < 64; i++)
            acc += sc[i] * invD * g_pctx[(size_t)(b * 64 + i) * HID + t];
        ctx[b * HID + t] = acc;
    }
}

// ---------------------------------------------------------------------------
extern "C" void kernel_launch(void* const* d_in, const int* in_sizes, int n_in,
                              void* d_out, int out_size) {
    const float* hidden = (const float*)d_in[0];  // (1,32,256)
    const float* enc    = (const float*)d_in[1];  // (32,8192,256)
    const float* W      = (const float*)d_in[2];  // (256,512)
    const float* bias   = (const float*)d_in[3];  // (256,)
    const float* v      = (const float*)d_in[4];  // (256,)

    float* out  = (float*)d_out;
    float* ctx  = out;            // (32,256) first
    float* attn = out + NB * HID; // (32,8192) second

    cudaFuncSetAttribute(main_mma_kernel,
                         cudaFuncAttributeMaxDynamicSharedMemorySize, SMEM_MAIN);

    prep_kernel<<<256, 256>>>(W, hidden, bias);
    main_mma_kernel<<<GRID_MAIN, 256, SMEM_MAIN>>>(enc, v, attn);
    finalize_kernel<<<dim3(NB, 8), 256>>>(attn, ctx);
}